// round 4
// baseline (speedup 1.0000x reference)
#include <cuda_runtime.h>
#include <cuda_fp16.h>

#define TB      131072
#define TSTEPS  256
#define BATCH   512
#define HH      128

__device__ __align__(16) float  g_f1 [TB * 256];
__device__ __align__(16) float  g_f2 [TB * 256];
__device__ __align__(16) float  g_f3 [TB * 128];
__device__ __align__(16) float  g_hid[TB * 24];
__device__ __align__(16) float  g_xg [TB * 512];
__device__ __align__(16) float  g_w1s[256 * 25];
__device__ __align__(16) float  g_wls[8];
__device__ __align__(16) float  g_bg [512];
__device__ __align__(16) __half g_whh[512 * 136];

__global__ void prep_kernel(const float* __restrict__ Wv1,
                            const float* __restrict__ Wl,
                            const float* __restrict__ bih,
                            const float* __restrict__ bhh,
                            const float* __restrict__ Whh)
{
    int i = blockIdx.x * blockDim.x + threadIdx.x;
    if (i < 6400)  g_w1s[i] = Wv1[i] * (1.0f / 255.0f);
    if (i < 8)     g_wls[i] = Wl[i] * 0.1f;
    if (i < 512)   g_bg[i]  = bih[i] + bhh[i];
    if (i < 65536) g_whh[(i >> 7) * 136 + (i & 127)] = __float2half(Whh[i]);
}

// C[M,N] = op(A[M,K] @ W[N,K]^T + bias); BM=128 BN=64 BK=16, 256 thr, 8x4 microtile
template<bool RELU>
__global__ void __launch_bounds__(256)
gemm_kernel(const float* __restrict__ A, const float* __restrict__ W,
            const float* __restrict__ bias, float* __restrict__ C,
            int K, int N, int ldc)
{
    __shared__ float As[16][132];
    __shared__ float Ws[16][68];
    const int tid = threadIdx.x;
    const int tx  = tid & 15;
    const int ty  = tid >> 4;
    const int m0  = blockIdx.x * 128;
    const int n0  = blockIdx.y * 64;

    float acc[8][4];
    #pragma unroll
    for (int i = 0; i < 8; i++)
        #pragma unroll
        for (int j = 0; j < 4; j++) acc[i][j] = 0.f;

    for (int kt = 0; kt < K; kt += 16) {
        #pragma unroll
        for (int i = 0; i < 8; i++) {
            int e = tid + 256 * i, m = e >> 4, kc = e & 15, k = kt + kc;
            As[kc][m] = (k < K) ? A[(m0 + m) * K + k] : 0.f;
        }
        #pragma unroll
        for (int i = 0; i < 4; i++) {
            int e = tid + 256 * i, n = e >> 4, kc = e & 15, k = kt + kc;
            Ws[kc][n] = (k < K && (n0 + n) < N) ? W[(n0 + n) * K + k] : 0.f;
        }
        __syncthreads();
        #pragma unroll
        for (int kl = 0; kl < 16; kl++) {
            float4 a0 = *(const float4*)&As[kl][ty * 8];
            float4 a1 = *(const float4*)&As[kl][ty * 8 + 4];
            float4 b0 = *(const float4*)&Ws[kl][tx * 4];
            float a[8] = {a0.x, a0.y, a0.z, a0.w, a1.x, a1.y, a1.z, a1.w};
            float b[4] = {b0.x, b0.y, b0.z, b0.w};
            #pragma unroll
            for (int i = 0; i < 8; i++)
                #pragma unroll
                for (int j = 0; j < 4; j++) acc[i][j] += a[i] * b[j];
        }
        __syncthreads();
    }

    int n = n0 + tx * 4;
    if (n >= N) return;
    float4 bv = *(const float4*)&bias[n];
    #pragma unroll
    for (int i = 0; i < 8; i++) {
        int row = m0 + ty * 8 + i;
        float4 v;
        v.x = acc[i][0] + bv.x; v.y = acc[i][1] + bv.y;
        v.z = acc[i][2] + bv.z; v.w = acc[i][3] + bv.w;
        if (RELU) {
            v.x = fmaxf(v.x, 0.f); v.y = fmaxf(v.y, 0.f);
            v.z = fmaxf(v.z, 0.f); v.w = fmaxf(v.w, 0.f);
        }
        *(float4*)&C[row * ldc + n] = v;
    }
}

__global__ void locmsg_kernel(const float* __restrict__ loc,
                              const float* __restrict__ msg,
                              const int*   __restrict__ done,
                              const float* __restrict__ bl,
                              const float* __restrict__ Wm,
                              const float* __restrict__ bm)
{
    int i = blockIdx.x * blockDim.x + threadIdx.x;
    if (i >= TB) return;
    float lx = loc[2 * i], ly = loc[2 * i + 1];
    float m  = (1.f - (float)done[i]) * msg[i];
    float* o = g_hid + i * 24 + 16;
    #pragma unroll
    for (int c = 0; c < 4; c++)
        o[c] = g_wls[2 * c] * lx + g_wls[2 * c + 1] * ly + bl[c];
    #pragma unroll
    for (int c = 0; c < 4; c++)
        o[4 + c] = fmaxf(Wm[c] * m + bm[c], 0.f);
}

__device__ __forceinline__ float sigf(float x) { return 1.f / (1.f + __expf(-x)); }

__global__ void __launch_bounds__(256)
lstm_kernel(const int*   __restrict__ done,
            const float* __restrict__ h0,
            const float* __restrict__ c0,
            float* __restrict__ out_nh,
            float* __restrict__ out_h,
            float* __restrict__ out_c)
{
    extern __shared__ unsigned char sraw[];
    __half* s_w    = (__half*)sraw;                               // 512*136*2 = 139264 B
    float*  s_h    = (float*)(sraw + 512 * 136 * 2);              // 512 floats
    float*  s_part = (float*)(sraw + 512 * 136 * 2 + 512 * 4);    // 128*20 floats

    const int tid = threadIdx.x;
    const int u   = tid & 127;
    const int kh  = tid >> 7;
    const int b0  = blockIdx.x * 4;

    {   // stage Whh into smem
        const uint4* src = (const uint4*)g_whh;
        uint4* dst = (uint4*)s_w;
        for (int i = tid; i < 512 * 136 * 2 / 16; i += 256) dst[i] = src[i];
    }
    for (int idx = tid; idx < 512; idx += 256) {
        int b = idx >> 7, uu = idx & 127;
        float m = 1.f - (float)done[b0 + b];
        s_h[idx] = h0[(b0 + b) * 128 + uu] * m;
    }
    float c[4], xc[16], xn[16];
    int dn[4];
    if (kh == 0) {
        #pragma unroll
        for (int b = 0; b < 4; b++) {
            float m = 1.f - (float)done[b0 + b];
            c[b] = c0[(b0 + b) * 128 + u] * m;
        }
        #pragma unroll
        for (int g = 0; g < 4; g++)
            #pragma unroll
            for (int b = 0; b < 4; b++)
                xc[g * 4 + b] = g_xg[(b0 + b) * 512 + g * 128 + u];
    }
    __syncthreads();

    const int k0 = kh * 64;
    for (int t = 0; t < TSTEPS; t++) {
        if (kh == 0 && t < TSTEPS - 1) {
            #pragma unroll
            for (int g = 0; g < 4; g++)
                #pragma unroll
                for (int b = 0; b < 4; b++)
                    xn[g * 4 + b] = g_xg[((t + 1) * BATCH + b0 + b) * 512 + g * 128 + u];
            #pragma unroll
            for (int b = 0; b < 4; b++) dn[b] = done[(t + 1) * BATCH + b0 + b];
        }

        float acc[16];
        #pragma unroll
        for (int i = 0; i < 16; i++) acc[i] = (kh == 0) ? xc[i] : 0.f;

        #pragma unroll
        for (int kk = 0; kk < 64; kk += 8) {
            int k = k0 + kk;
            float4 ha[4], hb[4];
            #pragma unroll
            for (int b = 0; b < 4; b++) {
                ha[b] = *(const float4*)&s_h[b * 128 + k];
                hb[b] = *(const float4*)&s_h[b * 128 + k + 4];
            }
            #pragma unroll
            for (int g = 0; g < 4; g++) {
                uint4 wv = *(const uint4*)&s_w[(u + (g << 7)) * 136 + k];
                const __half2* wh = (const __half2*)&wv;
                float2 w0 = __half22float2(wh[0]);
                float2 w1 = __half22float2(wh[1]);
                float2 w2 = __half22float2(wh[2]);
                float2 w3 = __half22float2(wh[3]);
                #pragma unroll
                for (int b = 0; b < 4; b++) {
                    float s = acc[g * 4 + b];
                    s += w0.x * ha[b].x; s += w0.y * ha[b].y;
                    s += w1.x * ha[b].z; s += w1.y * ha[b].w;
                    s += w2.x * hb[b].x; s += w2.y * hb[b].y;
                    s += w3.x * hb[b].z; s += w3.y * hb[b].w;
                    acc[g * 4 + b] = s;
                }
            }
        }

        if (kh == 1) {
            #pragma unroll
            for (int i = 0; i < 16; i += 4)
                *(float4*)&s_part[u * 20 + i] = *(float4*)&acc[i];
        }
        __syncthreads();

        if (kh == 0) {
            #pragma unroll
            for (int i = 0; i < 16; i++) acc[i] += s_part[u * 20 + i];
            #pragma unroll
            for (int b = 0; b < 4; b++) {
                float ig = sigf(acc[0 * 4 + b]);
                float fg = sigf(acc[1 * 4 + b]);
                float gg = tanhf(acc[2 * 4 + b]);
                float og = sigf(acc[3 * 4 + b]);
                float cn = fg * c[b] + ig * gg;
                float hn = og * tanhf(cn);
                out_nh[(t * BATCH + b0 + b) * 128 + u] = hn;
                if (t < TSTEPS - 1) {
                    float m = 1.f - (float)dn[b];
                    c[b] = cn * m;
                    s_h[b * 128 + u] = hn * m;
                } else {
                    out_h[(b0 + b) * 128 + u] = hn;
                    out_c[(b0 + b) * 128 + u] = cn;
                }
            }
            if (t < TSTEPS - 1) {
                #pragma unroll
                for (int i = 0; i < 16; i++) xc[i] = xn[i];
            }
        }
        __syncthreads();
    }
}

extern "C" void kernel_launch(void* const* d_in, const int* in_sizes, int n_in,
                              void* d_out, int out_size)
{
    const float* image    = (const float*)d_in[0];
    const float* location = (const float*)d_in[1];
    const float* message  = (const float*)d_in[2];
    const int*   done     = (const int*)  d_in[3];
    const float* h0       = (const float*)d_in[4];
    const float* c0       = (const float*)d_in[5];
    const float* Wv1      = (const float*)d_in[6];
    const float* bv1      = (const float*)d_in[7];
    const float* Wv2      = (const float*)d_in[8];
    const float* bv2      = (const float*)d_in[9];
    const float* Wv3      = (const float*)d_in[10];
    const float* bv3      = (const float*)d_in[11];
    const float* Wv4      = (const float*)d_in[12];
    const float* bv4      = (const float*)d_in[13];
    const float* Wl       = (const float*)d_in[14];
    const float* bl       = (const float*)d_in[15];
    const float* Wm       = (const float*)d_in[16];
    const float* bm       = (const float*)d_in[17];
    const float* Wih      = (const float*)d_in[18];
    // d_in[19] = bih, d_in[20] = Whh, d_in[21] = bhh
    const float* bih      = (const float*)d_in[19];
    const float* Whh      = (const float*)d_in[20];
    const float* bhh      = (const float*)d_in[21];

    float* out_nh = (float*)d_out;                 // [TB,128]
    float* out_h  = out_nh + (size_t)TB * 128;     // [B,128]
    float* out_c  = out_h + (size_t)BATCH * 128;   // [B,128]

    float* w1s = nullptr; float* bg = nullptr;
    cudaGetSymbolAddress((void**)&w1s, g_w1s);
    cudaGetSymbolAddress((void**)&bg,  g_bg);
    float* f1 = nullptr; float* f2 = nullptr; float* f3 = nullptr;
    float* hid = nullptr; float* xg = nullptr;
    cudaGetSymbolAddress((void**)&f1,  g_f1);
    cudaGetSymbolAddress((void**)&f2,  g_f2);
    cudaGetSymbolAddress((void**)&f3,  g_f3);
    cudaGetSymbolAddress((void**)&hid, g_hid);
    cudaGetSymbolAddress((void**)&xg,  g_xg);

    prep_kernel<<<256, 256>>>(Wv1, Wl, bih, bhh, Whh);

    dim3 blk(256);
    gemm_kernel<true ><<<dim3(TB / 128, 4), blk>>>(image, w1s, bv1, f1, 25, 256, 256);
    gemm_kernel<true ><<<dim3(TB / 128, 4), blk>>>(f1, Wv2, bv2, f2, 256, 256, 256);
    gemm_kernel<true ><<<dim3(TB / 128, 2), blk>>>(f2, Wv3, bv3, f3, 256, 128, 128);
    gemm_kernel<true ><<<dim3(TB / 128, 1), blk>>>(f3, Wv4, bv4, hid, 128, 16, 24);
    locmsg_kernel<<<(TB + 255) / 256, 256>>>(location, message, done, bl, Wm, bm);
    gemm_kernel<false><<<dim3(TB / 128, 8), blk>>>(hid, Wih, bg, xg, 24, 512, 512);

    const int lstm_smem = 512 * 136 * 2 + 512 * 4 + 128 * 20 * 4;  // 151552 B
    cudaFuncSetAttribute(lstm_kernel, cudaFuncAttributeMaxDynamicSharedMemorySize, lstm_smem);
    lstm_kernel<<<BATCH / 4, 256, lstm_smem>>>(done, h0, c0, out_nh, out_h, out_c);
}

// round 10
// speedup vs baseline: 1.4515x; 1.4515x over previous
#include <cuda_runtime.h>
#include <cuda_fp16.h>
#include <mma.h>
#include <cstdint>

using namespace nvcuda;

#define TB      131072
#define TSTEPS  256
#define BATCH   512

// ---------------- device scratch (no allocation allowed) ----------------
__device__ __align__(16) __half g_imgH[TB * 32];
__device__ __align__(16) __half g_f1H [TB * 256];
__device__ __align__(16) __half g_f2H [TB * 256];
__device__ __align__(16) __half g_f3H [TB * 128];
__device__ __align__(16) __half g_hidH[TB * 32];
__device__ __align__(16) float  g_xg  [TB * 512];
__device__ __align__(16) __half g_W1H [256 * 32];
__device__ __align__(16) __half g_W2H [256 * 256];
__device__ __align__(16) __half g_W3H [128 * 256];
__device__ __align__(16) __half g_W4H [16 * 128];
__device__ __align__(16) __half g_WihH[512 * 32];
__device__ __align__(16) float  g_bg  [512];
__device__ __align__(16) __half g_whh [512 * 136];

// ---------------- WMMA fp16 GEMM: C[M,N] = op(A[M,K] @ W[N,K]^T + bias) ----------------
// CTA tile 128x128, 8 warps of 32x64 (2x4 wmma frags), BK=64, fp32 accumulate.
// smem: A/B tiles (128x72 halves each) reused after mainloop as 128x132 fp32 staging.
template<bool RELU, bool OUTF32>
__global__ void __launch_bounds__(256)
gemm_wmma(const __half* __restrict__ A, const __half* __restrict__ Bw,
          const float* __restrict__ bias, void* __restrict__ Cout,
          int K, int Nvalid, int ldc)
{
    extern __shared__ __align__(16) unsigned char sm[];
    __half* s_a = (__half*)sm;              // 128 x 72 halves = 18432 B
    __half* s_b = s_a + 128 * 72;           // 128 x 72 halves = 18432 B
    float*  s_c = (float*)sm;               // reuse: 128 x 132 floats = 67584 B

    const int tid = threadIdx.x, w = tid >> 5;
    const int m0 = blockIdx.x * 128, n0 = blockIdx.y * 128;
    const int wm = (w & 3) * 32;            // warp m-offset in tile
    const int wn = (w >> 2) * 64;           // warp n-offset in tile

    wmma::fragment<wmma::accumulator, 16, 16, 16, float> acc[2][4];
    #pragma unroll
    for (int i = 0; i < 2; i++)
        #pragma unroll
        for (int j = 0; j < 4; j++) wmma::fill_fragment(acc[i][j], 0.f);

    for (int k0 = 0; k0 < K; k0 += 64) {
        int kw = K - k0; if (kw > 64) kw = 64;           // 32 or 64 (K multiple of 32)
        const int cpr = kw >> 3;                          // uint4 chunks per row
        // A tile: 128 rows x kw cols
        for (int i = tid; i < 128 * cpr; i += 256) {
            int r = i / cpr, c = (i - r * cpr) << 3;
            *(uint4*)(s_a + r * 72 + c) =
                *(const uint4*)(A + (size_t)(m0 + r) * K + k0 + c);
        }
        // B tile: 128 W-rows x kw cols (zero-fill rows beyond Nvalid)
        for (int i = tid; i < 128 * cpr; i += 256) {
            int r = i / cpr, c = (i - r * cpr) << 3;
            uint4 v = make_uint4(0, 0, 0, 0);
            if (n0 + r < Nvalid)
                v = *(const uint4*)(Bw + (size_t)(n0 + r) * K + k0 + c);
            *(uint4*)(s_b + r * 72 + c) = v;
        }
        __syncthreads();

        const int steps = kw >> 4;
        for (int s = 0; s < steps; s++) {
            const int kk = s * 16;
            wmma::fragment<wmma::matrix_a, 16, 16, 16, half, wmma::row_major> af[2];
            wmma::fragment<wmma::matrix_b, 16, 16, 16, half, wmma::col_major> bf[4];
            #pragma unroll
            for (int i = 0; i < 2; i++)
                wmma::load_matrix_sync(af[i], s_a + (wm + i * 16) * 72 + kk, 72);
            #pragma unroll
            for (int j = 0; j < 4; j++)
                wmma::load_matrix_sync(bf[j], s_b + (wn + j * 16) * 72 + kk, 72);
            #pragma unroll
            for (int i = 0; i < 2; i++)
                #pragma unroll
                for (int j = 0; j < 4; j++)
                    wmma::mma_sync(acc[i][j], af[i], bf[j], acc[i][j]);
        }
        __syncthreads();
    }

    // stage accumulators to smem (tiles no longer needed)
    #pragma unroll
    for (int i = 0; i < 2; i++)
        #pragma unroll
        for (int j = 0; j < 4; j++)
            wmma::store_matrix_sync(s_c + (wm + i * 16) * 132 + wn + j * 16,
                                    acc[i][j], 132, wmma::mem_row_major);
    __syncthreads();

    // epilogue: bias + relu + convert + store. thread -> (row, 64-col half)
    const int r  = tid >> 1;
    const int ch = (tid & 1) << 6;
    const int row = m0 + r;
    int ncols = Nvalid - n0; if (ncols > 128) ncols = 128;

    if (OUTF32) {
        float* cp = (float*)Cout + (size_t)row * ldc + n0;
        #pragma unroll
        for (int q = 0; q < 16; q++) {
            int c0 = ch + q * 4;
            if (c0 >= ncols) break;
            float4 v;
            v.x = s_c[r * 132 + c0 + 0] + __ldg(bias + n0 + c0 + 0);
            v.y = s_c[r * 132 + c0 + 1] + __ldg(bias + n0 + c0 + 1);
            v.z = s_c[r * 132 + c0 + 2] + __ldg(bias + n0 + c0 + 2);
            v.w = s_c[r * 132 + c0 + 3] + __ldg(bias + n0 + c0 + 3);
            if (RELU) {
                v.x = fmaxf(v.x, 0.f); v.y = fmaxf(v.y, 0.f);
                v.z = fmaxf(v.z, 0.f); v.w = fmaxf(v.w, 0.f);
            }
            *(float4*)(cp + c0) = v;
        }
    } else {
        __half* cp = (__half*)Cout + (size_t)row * ldc + n0;
        #pragma unroll
        for (int q = 0; q < 8; q++) {
            int c0 = ch + q * 8;
            if (c0 >= ncols) break;
            __half2 hh[4];
            #pragma unroll
            for (int e = 0; e < 4; e++) {
                float x0 = s_c[r * 132 + c0 + 2 * e]     + __ldg(bias + n0 + c0 + 2 * e);
                float x1 = s_c[r * 132 + c0 + 2 * e + 1] + __ldg(bias + n0 + c0 + 2 * e + 1);
                if (RELU) { x0 = fmaxf(x0, 0.f); x1 = fmaxf(x1, 0.f); }
                hh[e] = __floats2half2_rn(x0, x1);
            }
            *(uint4*)(cp + c0) = *(uint4*)hh;
        }
    }
}

// ---------------- prep: fp16 weights (padded), bg, Whh-fp16 ----------------
__global__ void prep_weights(const float* __restrict__ Wv1, const float* __restrict__ Wv2,
                             const float* __restrict__ Wv3, const float* __restrict__ Wv4,
                             const float* __restrict__ Wih, const float* __restrict__ bih,
                             const float* __restrict__ bhh, const float* __restrict__ Whh)
{
    int i = blockIdx.x * blockDim.x + threadIdx.x;
    if (i < 65536) {
        g_whh[(i >> 7) * 136 + (i & 127)] = __float2half(Whh[i]);
        g_W2H[i] = __float2half(Wv2[i]);
    }
    if (i < 32768) g_W3H[i] = __float2half(Wv3[i]);
    if (i < 2048)  g_W4H[i] = __float2half(Wv4[i]);
    if (i < 8192) {                       // W1 pad 25 -> 32
        int r = i >> 5, c = i & 31;
        g_W1H[i] = (c < 25) ? __float2half(Wv1[r * 25 + c]) : __half(0.f);
    }
    if (i < 16384) {                      // Wih pad 24 -> 32
        int r = i >> 5, c = i & 31;
        g_WihH[i] = (c < 24) ? __float2half(Wih[r * 24 + c]) : __half(0.f);
    }
    if (i < 512) g_bg[i] = bih[i] + bhh[i];
}

__global__ void prep_img(const float* __restrict__ image)
{
    int i = blockIdx.x * blockDim.x + threadIdx.x;   // TB*32 threads
    int r = i >> 5, c = i & 31;
    g_imgH[i] = (c < 25) ? __float2half(image[r * 25 + c] * (1.0f / 255.0f)) : __half(0.f);
}

__global__ void locmsg_h(const float* __restrict__ loc, const float* __restrict__ msg,
                         const int* __restrict__ done,
                         const float* __restrict__ Wl, const float* __restrict__ bl,
                         const float* __restrict__ Wm, const float* __restrict__ bm)
{
    int i = blockIdx.x * blockDim.x + threadIdx.x;
    if (i >= TB) return;
    float lx = loc[2 * i] * 0.1f, ly = loc[2 * i + 1] * 0.1f;
    float m = (1.f - (float)done[i]) * msg[i];
    __half h[16];
    #pragma unroll
    for (int c = 0; c < 4; c++) h[c] = __float2half(Wl[2*c] * lx + Wl[2*c+1] * ly + bl[c]);
    #pragma unroll
    for (int c = 0; c < 4; c++) h[4 + c] = __float2half(fmaxf(Wm[c] * m + bm[c], 0.f));
    #pragma unroll
    for (int c = 8; c < 16; c++) h[c] = __half(0.f);
    uint4* dst = (uint4*)(g_hidH + (size_t)i * 32 + 16);
    dst[0] = *(uint4*)&h[0];
    dst[1] = *(uint4*)&h[8];
}

// ---------------- persistent LSTM (unchanged from passing R4 kernel) ----------------
__device__ __forceinline__ float sigf(float x) { return 1.f / (1.f + __expf(-x)); }

__global__ void __launch_bounds__(256)
lstm_kernel(const int*   __restrict__ done,
            const float* __restrict__ h0,
            const float* __restrict__ c0,
            float* __restrict__ out_nh,
            float* __restrict__ out_h,
            float* __restrict__ out_c)
{
    extern __shared__ unsigned char sraw[];
    __half* s_w    = (__half*)sraw;                               // 512*136*2 = 139264 B
    float*  s_h    = (float*)(sraw + 512 * 136 * 2);              // 512 floats
    float*  s_part = (float*)(sraw + 512 * 136 * 2 + 512 * 4);    // 128*20 floats

    const int tid = threadIdx.x;
    const int u   = tid & 127;
    const int kh  = tid >> 7;
    const int b0  = blockIdx.x * 4;

    {
        const uint4* src = (const uint4*)g_whh;
        uint4* dst = (uint4*)s_w;
        for (int i = tid; i < 512 * 136 * 2 / 16; i += 256) dst[i] = src[i];
    }
    for (int idx = tid; idx < 512; idx += 256) {
        int b = idx >> 7, uu = idx & 127;
        float m = 1.f - (float)done[b0 + b];
        s_h[idx] = h0[(b0 + b) * 128 + uu] * m;
    }
    float c[4], xc[16], xn[16];
    int dn[4];
    if (kh == 0) {
        #pragma unroll
        for (int b = 0; b < 4; b++) {
            float m = 1.f - (float)done[b0 + b];
            c[b] = c0[(b0 + b) * 128 + u] * m;
        }
        #pragma unroll
        for (int g = 0; g < 4; g++)
            #pragma unroll
            for (int b = 0; b < 4; b++)
                xc[g * 4 + b] = g_xg[(b0 + b) * 512 + g * 128 + u];
    }
    __syncthreads();

    const int k0 = kh * 64;
    for (int t = 0; t < TSTEPS; t++) {
        if (kh == 0 && t < TSTEPS - 1) {
            #pragma unroll
            for (int g = 0; g < 4; g++)
                #pragma unroll
                for (int b = 0; b < 4; b++)
                    xn[g * 4 + b] = g_xg[((t + 1) * BATCH + b0 + b) * 512 + g * 128 + u];
            #pragma unroll
            for (int b = 0; b < 4; b++) dn[b] = done[(t + 1) * BATCH + b0 + b];
        }

        float acc[16];
        #pragma unroll
        for (int i = 0; i < 16; i++) acc[i] = (kh == 0) ? xc[i] : 0.f;

        #pragma unroll
        for (int kk = 0; kk < 64; kk += 8) {
            int k = k0 + kk;
            float4 ha[4], hb[4];
            #pragma unroll
            for (int b = 0; b < 4; b++) {
                ha[b] = *(const float4*)&s_h[b * 128 + k];
                hb[b] = *(const float4*)&s_h[b * 128 + k + 4];
            }
            #pragma unroll
            for (int g = 0; g < 4; g++) {
                uint4 wv = *(const uint4*)&s_w[(u + (g << 7)) * 136 + k];
                const __half2* wh = (const __half2*)&wv;
                float2 w0 = __half22float2(wh[0]);
                float2 w1 = __half22float2(wh[1]);
                float2 w2 = __half22float2(wh[2]);
                float2 w3 = __half22float2(wh[3]);
                #pragma unroll
                for (int b = 0; b < 4; b++) {
                    float s = acc[g * 4 + b];
                    s += w0.x * ha[b].x; s += w0.y * ha[b].y;
                    s += w1.x * ha[b].z; s += w1.y * ha[b].w;
                    s += w2.x * hb[b].x; s += w2.y * hb[b].y;
                    s += w3.x * hb[b].z; s += w3.y * hb[b].w;
                    acc[g * 4 + b] = s;
                }
            }
        }

        if (kh == 1) {
            #pragma unroll
            for (int i = 0; i < 16; i += 4)
                *(float4*)&s_part[u * 20 + i] = *(float4*)&acc[i];
        }
        __syncthreads();

        if (kh == 0) {
            #pragma unroll
            for (int i = 0; i < 16; i++) acc[i] += s_part[u * 20 + i];
            #pragma unroll
            for (int b = 0; b < 4; b++) {
                float ig = sigf(acc[0 * 4 + b]);
                float fg = sigf(acc[1 * 4 + b]);
                float gg = tanhf(acc[2 * 4 + b]);
                float og = sigf(acc[3 * 4 + b]);
                float cn = fg * c[b] + ig * gg;
                float hn = og * tanhf(cn);
                out_nh[(t * BATCH + b0 + b) * 128 + u] = hn;
                if (t < TSTEPS - 1) {
                    float m = 1.f - (float)dn[b];
                    c[b] = cn * m;
                    s_h[b * 128 + u] = hn * m;
                } else {
                    out_h[(b0 + b) * 128 + u] = hn;
                    out_c[(b0 + b) * 128 + u] = cn;
                }
            }
            if (t < TSTEPS - 1) {
                #pragma unroll
                for (int i = 0; i < 16; i++) xc[i] = xn[i];
            }
        }
        __syncthreads();
    }
}

// ---------------- launcher ----------------
extern "C" void kernel_launch(void* const* d_in, const int* in_sizes, int n_in,
                              void* d_out, int out_size)
{
    const float* image    = (const float*)d_in[0];
    const float* location = (const float*)d_in[1];
    const float* message  = (const float*)d_in[2];
    const int*   done     = (const int*)  d_in[3];
    const float* h0       = (const float*)d_in[4];
    const float* c0       = (const float*)d_in[5];
    const float* Wv1      = (const float*)d_in[6];
    const float* bv1      = (const float*)d_in[7];
    const float* Wv2      = (const float*)d_in[8];
    const float* bv2      = (const float*)d_in[9];
    const float* Wv3      = (const float*)d_in[10];
    const float* bv3      = (const float*)d_in[11];
    const float* Wv4      = (const float*)d_in[12];
    const float* bv4      = (const float*)d_in[13];
    const float* Wl       = (const float*)d_in[14];
    const float* bl       = (const float*)d_in[15];
    const float* Wm       = (const float*)d_in[16];
    const float* bm       = (const float*)d_in[17];
    const float* Wih      = (const float*)d_in[18];
    const float* bih      = (const float*)d_in[19];
    const float* Whh      = (const float*)d_in[20];
    const float* bhh      = (const float*)d_in[21];

    float* out_nh = (float*)d_out;
    float* out_h  = out_nh + (size_t)TB * 128;
    float* out_c  = out_h + (size_t)BATCH * 128;

    void *imgH, *f1H, *f2H, *f3H, *hidH, *xg, *W1H, *W2H, *W3H, *W4H, *WihH, *bg;
    cudaGetSymbolAddress(&imgH, g_imgH);
    cudaGetSymbolAddress(&f1H,  g_f1H);
    cudaGetSymbolAddress(&f2H,  g_f2H);
    cudaGetSymbolAddress(&f3H,  g_f3H);
    cudaGetSymbolAddress(&hidH, g_hidH);
    cudaGetSymbolAddress(&xg,   g_xg);
    cudaGetSymbolAddress(&W1H,  g_W1H);
    cudaGetSymbolAddress(&W2H,  g_W2H);
    cudaGetSymbolAddress(&W3H,  g_W3H);
    cudaGetSymbolAddress(&W4H,  g_W4H);
    cudaGetSymbolAddress(&WihH, g_WihH);
    cudaGetSymbolAddress(&bg,   g_bg);

    const int gsm = 128 * 132 * 4;       // 67584 B
    cudaFuncSetAttribute(gemm_wmma<true,  false>, cudaFuncAttributeMaxDynamicSharedMemorySize, gsm);
    cudaFuncSetAttribute(gemm_wmma<false, true >, cudaFuncAttributeMaxDynamicSharedMemorySize, gsm);
    cudaFuncSetAttribute(lstm_kernel, cudaFuncAttributeMaxDynamicSharedMemorySize, 151552);

    prep_weights<<<256, 256>>>(Wv1, Wv2, Wv3, Wv4, Wih, bih, bhh, Whh);
    prep_img<<<TB * 32 / 256, 256>>>(image);

    gemm_wmma<true,  false><<<dim3(1024, 2), 256, gsm>>>((const __half*)imgH, (const __half*)W1H, bv1, f1H,  32, 256, 256);
    gemm_wmma<true,  false><<<dim3(1024, 2), 256, gsm>>>((const __half*)f1H,  (const __half*)W2H, bv2, f2H, 256, 256, 256);
    gemm_wmma<true,  false><<<dim3(1024, 1), 256, gsm>>>((const __half*)f2H,  (const __half*)W3H, bv3, f3H, 256, 128, 128);
    gemm_wmma<true,  false><<<dim3(1024, 1), 256, gsm>>>((const __half*)f3H,  (const __half*)W4H, bv4, hidH, 128, 16, 32);
    locmsg_h<<<(TB + 255) / 256, 256>>>(location, message, done, Wl, bl, Wm, bm);
    gemm_wmma<false, true ><<<dim3(1024, 4), 256, gsm>>>((const __half*)hidH, (const __half*)WihH, (const float*)bg, xg, 32, 512, 512);

    const int lstm_smem = 512 * 136 * 2 + 512 * 4 + 128 * 20 * 4;
    lstm_kernel<<<BATCH / 4, 256, lstm_smem>>>(done, h0, c0, out_nh, out_h, out_c);
}

// round 11
// speedup vs baseline: 1.6534x; 1.1392x over previous
#include <cuda_runtime.h>
#include <cuda_fp16.h>
#include <mma.h>
#include <cstdint>

using namespace nvcuda;

#define TB      131072
#define TSTEPS  256
#define BATCH   512

// ---------------- device scratch (no allocation allowed) ----------------
__device__ __align__(16) __half g_imgH[TB * 32];
__device__ __align__(16) __half g_f1H [TB * 256];
__device__ __align__(16) __half g_f2H [TB * 256];
__device__ __align__(16) __half g_f3H [TB * 128];
__device__ __align__(16) __half g_hidH[TB * 32];
__device__ __align__(16) float  g_xg  [TB * 512];
__device__ __align__(16) __half g_W1H [256 * 32];
__device__ __align__(16) __half g_W2H [256 * 256];
__device__ __align__(16) __half g_W3H [128 * 256];
__device__ __align__(16) __half g_W4H [16 * 128];
__device__ __align__(16) __half g_WihH[512 * 32];
__device__ __align__(16) float  g_bg  [512];
__device__ __align__(16) __half g_whh [512 * 136];

// ---------------- WMMA fp16 GEMM: C[M,N] = op(A[M,K] @ W[N,K]^T + bias) ----------------
template<bool RELU, bool OUTF32>
__global__ void __launch_bounds__(256)
gemm_wmma(const __half* __restrict__ A, const __half* __restrict__ Bw,
          const float* __restrict__ bias, void* __restrict__ Cout,
          int K, int Nvalid, int ldc)
{
    extern __shared__ __align__(16) unsigned char sm[];
    __half* s_a = (__half*)sm;              // 128 x 72 halves
    __half* s_b = s_a + 128 * 72;           // 128 x 72 halves
    float*  s_c = (float*)sm;               // reuse: 128 x 132 floats

    const int tid = threadIdx.x, w = tid >> 5;
    const int m0 = blockIdx.x * 128, n0 = blockIdx.y * 128;
    const int wm = (w & 3) * 32;
    const int wn = (w >> 2) * 64;

    wmma::fragment<wmma::accumulator, 16, 16, 16, float> acc[2][4];
    #pragma unroll
    for (int i = 0; i < 2; i++)
        #pragma unroll
        for (int j = 0; j < 4; j++) wmma::fill_fragment(acc[i][j], 0.f);

    for (int k0 = 0; k0 < K; k0 += 64) {
        int kw = K - k0; if (kw > 64) kw = 64;
        const int cpr = kw >> 3;
        for (int i = tid; i < 128 * cpr; i += 256) {
            int r = i / cpr, c = (i - r * cpr) << 3;
            *(uint4*)(s_a + r * 72 + c) =
                *(const uint4*)(A + (size_t)(m0 + r) * K + k0 + c);
        }
        for (int i = tid; i < 128 * cpr; i += 256) {
            int r = i / cpr, c = (i - r * cpr) << 3;
            uint4 v = make_uint4(0, 0, 0, 0);
            if (n0 + r < Nvalid)
                v = *(const uint4*)(Bw + (size_t)(n0 + r) * K + k0 + c);
            *(uint4*)(s_b + r * 72 + c) = v;
        }
        __syncthreads();

        const int steps = kw >> 4;
        for (int s = 0; s < steps; s++) {
            const int kk = s * 16;
            wmma::fragment<wmma::matrix_a, 16, 16, 16, half, wmma::row_major> af[2];
            wmma::fragment<wmma::matrix_b, 16, 16, 16, half, wmma::col_major> bf[4];
            #pragma unroll
            for (int i = 0; i < 2; i++)
                wmma::load_matrix_sync(af[i], s_a + (wm + i * 16) * 72 + kk, 72);
            #pragma unroll
            for (int j = 0; j < 4; j++)
                wmma::load_matrix_sync(bf[j], s_b + (wn + j * 16) * 72 + kk, 72);
            #pragma unroll
            for (int i = 0; i < 2; i++)
                #pragma unroll
                for (int j = 0; j < 4; j++)
                    wmma::mma_sync(acc[i][j], af[i], bf[j], acc[i][j]);
        }
        __syncthreads();
    }

    #pragma unroll
    for (int i = 0; i < 2; i++)
        #pragma unroll
        for (int j = 0; j < 4; j++)
            wmma::store_matrix_sync(s_c + (wm + i * 16) * 132 + wn + j * 16,
                                    acc[i][j], 132, wmma::mem_row_major);
    __syncthreads();

    const int r  = tid >> 1;
    const int ch = (tid & 1) << 6;
    const int row = m0 + r;
    int ncols = Nvalid - n0; if (ncols > 128) ncols = 128;

    if (OUTF32) {
        float* cp = (float*)Cout + (size_t)row * ldc + n0;
        #pragma unroll
        for (int q = 0; q < 16; q++) {
            int c0 = ch + q * 4;
            if (c0 >= ncols) break;
            float4 v;
            v.x = s_c[r * 132 + c0 + 0] + __ldg(bias + n0 + c0 + 0);
            v.y = s_c[r * 132 + c0 + 1] + __ldg(bias + n0 + c0 + 1);
            v.z = s_c[r * 132 + c0 + 2] + __ldg(bias + n0 + c0 + 2);
            v.w = s_c[r * 132 + c0 + 3] + __ldg(bias + n0 + c0 + 3);
            if (RELU) {
                v.x = fmaxf(v.x, 0.f); v.y = fmaxf(v.y, 0.f);
                v.z = fmaxf(v.z, 0.f); v.w = fmaxf(v.w, 0.f);
            }
            *(float4*)(cp + c0) = v;
        }
    } else {
        __half* cp = (__half*)Cout + (size_t)row * ldc + n0;
        #pragma unroll
        for (int q = 0; q < 8; q++) {
            int c0 = ch + q * 8;
            if (c0 >= ncols) break;
            __half2 hh[4];
            #pragma unroll
            for (int e = 0; e < 4; e++) {
                float x0 = s_c[r * 132 + c0 + 2 * e]     + __ldg(bias + n0 + c0 + 2 * e);
                float x1 = s_c[r * 132 + c0 + 2 * e + 1] + __ldg(bias + n0 + c0 + 2 * e + 1);
                if (RELU) { x0 = fmaxf(x0, 0.f); x1 = fmaxf(x1, 0.f); }
                hh[e] = __floats2half2_rn(x0, x1);
            }
            *(uint4*)(cp + c0) = *(uint4*)hh;
        }
    }
}

// ---------------- prep kernels ----------------
__global__ void prep_weights(const float* __restrict__ Wv1, const float* __restrict__ Wv2,
                             const float* __restrict__ Wv3, const float* __restrict__ Wv4,
                             const float* __restrict__ Wih, const float* __restrict__ bih,
                             const float* __restrict__ bhh, const float* __restrict__ Whh)
{
    int i = blockIdx.x * blockDim.x + threadIdx.x;
    if (i < 65536) {
        g_whh[(i >> 7) * 136 + (i & 127)] = __float2half(Whh[i]);
        g_W2H[i] = __float2half(Wv2[i]);
    }
    if (i < 32768) g_W3H[i] = __float2half(Wv3[i]);
    if (i < 2048)  g_W4H[i] = __float2half(Wv4[i]);
    if (i < 8192) {
        int r = i >> 5, c = i & 31;
        g_W1H[i] = (c < 25) ? __float2half(Wv1[r * 25 + c]) : __half(0.f);
    }
    if (i < 16384) {
        int r = i >> 5, c = i & 31;
        g_WihH[i] = (c < 24) ? __float2half(Wih[r * 24 + c]) : __half(0.f);
    }
    if (i < 512) g_bg[i] = bih[i] + bhh[i];
}

__global__ void prep_img(const float* __restrict__ image)
{
    int i = blockIdx.x * blockDim.x + threadIdx.x;
    int r = i >> 5, c = i & 31;
    g_imgH[i] = (c < 25) ? __float2half(image[r * 25 + c] * (1.0f / 255.0f)) : __half(0.f);
}

__global__ void locmsg_h(const float* __restrict__ loc, const float* __restrict__ msg,
                         const int* __restrict__ done,
                         const float* __restrict__ Wl, const float* __restrict__ bl,
                         const float* __restrict__ Wm, const float* __restrict__ bm)
{
    int i = blockIdx.x * blockDim.x + threadIdx.x;
    if (i >= TB) return;
    float lx = loc[2 * i] * 0.1f, ly = loc[2 * i + 1] * 0.1f;
    float m = (1.f - (float)done[i]) * msg[i];
    __half h[16];
    #pragma unroll
    for (int c = 0; c < 4; c++) h[c] = __float2half(Wl[2*c] * lx + Wl[2*c+1] * ly + bl[c]);
    #pragma unroll
    for (int c = 0; c < 4; c++) h[4 + c] = __float2half(fmaxf(Wm[c] * m + bm[c], 0.f));
    #pragma unroll
    for (int c = 8; c < 16; c++) h[c] = __half(0.f);
    uint4* dst = (uint4*)(g_hidH + (size_t)i * 32 + 16);
    dst[0] = *(uint4*)&h[0];
    dst[1] = *(uint4*)&h[8];
}

// ---------------- tensor-core LSTM: 64 CTAs x 8 batch, persistent B frags ----------------
__device__ __forceinline__ float sigf(float x) { return 1.f / (1.f + __expf(-x)); }

#define LSTM_LB 8

__global__ void __launch_bounds__(256, 1)
lstm_wmma(const int*   __restrict__ done,
          const float* __restrict__ h0,
          const float* __restrict__ c0,
          float* __restrict__ out_nh,
          float* __restrict__ out_h,
          float* __restrict__ out_c)
{
    extern __shared__ __align__(16) unsigned char sraw[];
    __half* s_w     = (__half*)sraw;                              // 512*136 h = 139264 B
    __half* s_h     = (__half*)(sraw + 139264);                   // 8*136 h  = 2176 B
    float*  s_gates = (float*)(sraw + 139264 + 2176);             // 8*516 f  = 16512 B
    float*  s_x     = (float*)(sraw + 139264 + 2176 + 16512);     // 8*512 f  = 16384 B

    const int tid = threadIdx.x, w = tid >> 5;
    const int b0  = blockIdx.x * LSTM_LB;
    const int u   = tid & 127;
    const int bg  = (tid >> 7) * 4;      // this thread's 4 batch rows: bg..bg+3
    const int n0  = w * 64;

    // stage Whh (already [512][136] fp16 in gmem)
    for (int i = tid; i < 512 * 136 * 2 / 16; i += 256)
        ((uint4*)s_w)[i] = ((const uint4*)g_whh)[i];
    // h0 masked -> fp16 smem
    for (int i = tid; i < LSTM_LB * 128; i += 256) {
        int b = i >> 7, uu = i & 127;
        float m = 1.f - (float)done[b0 + b];
        s_h[b * 136 + uu] = __float2half(h0[(b0 + b) * 128 + uu] * m);
    }
    // stage xg(t=0): rows (0*512 + b0 .. +7) are contiguous
    {
        const float4* src = (const float4*)(g_xg + (size_t)b0 * 512);
        #pragma unroll
        for (int i = 0; i < 4; i++)
            ((float4*)s_x)[tid + 256 * i] = src[tid + 256 * i];
    }
    float c[4];
    #pragma unroll
    for (int j = 0; j < 4; j++) {
        int b = bg + j;
        float m = 1.f - (float)done[b0 + b];
        c[j] = c0[(b0 + b) * 128 + u] * m;
    }
    __syncthreads();

    // persistent Whh fragments: 16 frags (8 k-steps x 2 n-frags of 32)
    wmma::fragment<wmma::matrix_b, 8, 32, 16, half, wmma::col_major> bf[16];
    #pragma unroll
    for (int k = 0; k < 8; k++)
        #pragma unroll
        for (int j = 0; j < 2; j++)
            wmma::load_matrix_sync(bf[k * 2 + j], s_w + (n0 + j * 32) * 136 + k * 16, 136);

    wmma::fragment<wmma::accumulator, 8, 32, 16, float> acc0, acc1;
    wmma::fragment<wmma::matrix_a, 8, 32, 16, half, wmma::row_major> af;

    for (int t = 0; t < TSTEPS; t++) {
        // prefetch next-step done masks (latency hidden under mma)
        float dm[4];
        if (t < TSTEPS - 1) {
            #pragma unroll
            for (int j = 0; j < 4; j++)
                dm[j] = 1.f - (float)done[(t + 1) * BATCH + b0 + bg + j];
        }

        wmma::fill_fragment(acc0, 0.f);
        wmma::fill_fragment(acc1, 0.f);
        #pragma unroll
        for (int k = 0; k < 8; k++) {
            wmma::load_matrix_sync(af, s_h + k * 16, 136);
            wmma::mma_sync(acc0, af, bf[k * 2 + 0], acc0);
            wmma::mma_sync(acc1, af, bf[k * 2 + 1], acc1);
        }
        wmma::store_matrix_sync(s_gates + n0,      acc0, 516, wmma::mem_row_major);
        wmma::store_matrix_sync(s_gates + n0 + 32, acc1, 516, wmma::mem_row_major);
        __syncthreads();

        // activation: 4 cells per thread (b = bg+j, unit u)
        #pragma unroll
        for (int j = 0; j < 4; j++) {
            int b = bg + j;
            const float* gp = s_gates + b * 516;
            const float* xp = s_x + b * 512;
            float ig = sigf (gp[u]       + xp[u]);
            float fg = sigf (gp[128 + u] + xp[128 + u]);
            float gg = tanhf(gp[256 + u] + xp[256 + u]);
            float og = sigf (gp[384 + u] + xp[384 + u]);
            float cn = fg * c[j] + ig * gg;
            float hn = og * tanhf(cn);
            out_nh[((size_t)t * BATCH + b0 + b) * 128 + u] = hn;
            if (t < TSTEPS - 1) {
                c[j] = cn * dm[j];
                s_h[b * 136 + u] = __float2half(hn * dm[j]);
            } else {
                out_h[(b0 + b) * 128 + u] = hn;
                out_c[(b0 + b) * 128 + u] = cn;
            }
        }
        __syncthreads();

        // copy xg(t+1) gmem->smem; LDG latency hides under next step's mma
        if (t < TSTEPS - 1) {
            const float4* src = (const float4*)(g_xg + ((size_t)(t + 1) * BATCH + b0) * 512);
            #pragma unroll
            for (int i = 0; i < 4; i++)
                ((float4*)s_x)[tid + 256 * i] = src[tid + 256 * i];
        }
    }
}

// ---------------- launcher ----------------
extern "C" void kernel_launch(void* const* d_in, const int* in_sizes, int n_in,
                              void* d_out, int out_size)
{
    const float* image    = (const float*)d_in[0];
    const float* location = (const float*)d_in[1];
    const float* message  = (const float*)d_in[2];
    const int*   done     = (const int*)  d_in[3];
    const float* h0       = (const float*)d_in[4];
    const float* c0       = (const float*)d_in[5];
    const float* Wv1      = (const float*)d_in[6];
    const float* bv1      = (const float*)d_in[7];
    const float* Wv2      = (const float*)d_in[8];
    const float* bv2      = (const float*)d_in[9];
    const float* Wv3      = (const float*)d_in[10];
    const float* bv3      = (const float*)d_in[11];
    const float* Wv4      = (const float*)d_in[12];
    const float* bv4      = (const float*)d_in[13];
    const float* Wl       = (const float*)d_in[14];
    const float* bl       = (const float*)d_in[15];
    const float* Wm       = (const float*)d_in[16];
    const float* bm       = (const float*)d_in[17];
    const float* Wih      = (const float*)d_in[18];
    const float* bih      = (const float*)d_in[19];
    const float* Whh      = (const float*)d_in[20];
    const float* bhh      = (const float*)d_in[21];

    float* out_nh = (float*)d_out;
    float* out_h  = out_nh + (size_t)TB * 128;
    float* out_c  = out_h + (size_t)BATCH * 128;

    void *imgH, *f1H, *f2H, *f3H, *hidH, *xg, *W1H, *W2H, *W3H, *W4H, *WihH, *bg;
    cudaGetSymbolAddress(&imgH, g_imgH);
    cudaGetSymbolAddress(&f1H,  g_f1H);
    cudaGetSymbolAddress(&f2H,  g_f2H);
    cudaGetSymbolAddress(&f3H,  g_f3H);
    cudaGetSymbolAddress(&hidH, g_hidH);
    cudaGetSymbolAddress(&xg,   g_xg);
    cudaGetSymbolAddress(&W1H,  g_W1H);
    cudaGetSymbolAddress(&W2H,  g_W2H);
    cudaGetSymbolAddress(&W3H,  g_W3H);
    cudaGetSymbolAddress(&W4H,  g_W4H);
    cudaGetSymbolAddress(&WihH, g_WihH);
    cudaGetSymbolAddress(&bg,   g_bg);

    const int gsm = 128 * 132 * 4;                       // 67584 B
    const int lsm = 139264 + 2176 + 16512 + 16384;       // 174336 B
    cudaFuncSetAttribute(gemm_wmma<true,  false>, cudaFuncAttributeMaxDynamicSharedMemorySize, gsm);
    cudaFuncSetAttribute(gemm_wmma<false, true >, cudaFuncAttributeMaxDynamicSharedMemorySize, gsm);
    cudaFuncSetAttribute(lstm_wmma, cudaFuncAttributeMaxDynamicSharedMemorySize, lsm);

    prep_weights<<<256, 256>>>(Wv1, Wv2, Wv3, Wv4, Wih, bih, bhh, Whh);
    prep_img<<<TB * 32 / 256, 256>>>(image);

    gemm_wmma<true,  false><<<dim3(1024, 2), 256, gsm>>>((const __half*)imgH, (const __half*)W1H, bv1, f1H,  32, 256, 256);
    gemm_wmma<true,  false><<<dim3(1024, 2), 256, gsm>>>((const __half*)f1H,  (const __half*)W2H, bv2, f2H, 256, 256, 256);
    gemm_wmma<true,  false><<<dim3(1024, 1), 256, gsm>>>((const __half*)f2H,  (const __half*)W3H, bv3, f3H, 256, 128, 128);
    gemm_wmma<true,  false><<<dim3(1024, 1), 256, gsm>>>((const __half*)f3H,  (const __half*)W4H, bv4, hidH, 128, 16, 32);
    locmsg_h<<<(TB + 255) / 256, 256>>>(location, message, done, Wl, bl, Wm, bm);
    gemm_wmma<false, true ><<<dim3(1024, 4), 256, gsm>>>((const __half*)hidH, (const __half*)WihH, (const float*)bg, xg, 32, 512, 512);

    lstm_wmma<<<BATCH / LSTM_LB, 256, lsm>>>(done, h0, c0, out_nh, out_h, out_c);
}